// round 1
// baseline (speedup 1.0000x reference)
#include <cuda_runtime.h>
#include <cstdint>

// CarryLSTMModel: B=8192, T=1024, D=16, H=16 (4H=64 gates, order i,f,g,o)
// One warp per batch element. Lane j owns gate columns j and j+32.
// Weights live in registers as f32x2 pairs over adjacent k; multiplicand pairs
// {v[k],v[k+1]} come packed for free from float4 loads (x from gmem, h from smem).
// Per step: 32x fma.rn.f32x2 (packed fp32, 2x fma-pipe throughput on sm_103a).

#define NB 8192
#define NT 1024
#define ND 16
#define NH 16
#define NG 64

typedef unsigned long long u64;
typedef unsigned int u32;

__device__ __forceinline__ u64 pack2(float lo, float hi) {
    u64 r;
    asm("mov.b64 %0, {%1, %2};" : "=l"(r) : "r"(__float_as_uint(lo)), "r"(__float_as_uint(hi)));
    return r;
}
__device__ __forceinline__ void unpack2(u64 v, float& lo, float& hi) {
    u32 a, b;
    asm("mov.b64 {%0, %1}, %2;" : "=r"(a), "=r"(b) : "l"(v));
    lo = __uint_as_float(a);
    hi = __uint_as_float(b);
}
__device__ __forceinline__ u64 ffma2(u64 a, u64 b, u64 c) {
    u64 d;
    asm("fma.rn.f32x2 %0, %1, %2, %3;" : "=l"(d) : "l"(a), "l"(b), "l"(c));
    return d;
}
__device__ __forceinline__ float ex2f(float x) {
    float r; asm("ex2.approx.f32 %0, %1;" : "=f"(r) : "f"(x)); return r;
}
__device__ __forceinline__ float rcpf(float x) {
    float r; asm("rcp.approx.f32 %0, %1;" : "=f"(r) : "f"(x)); return r;
}

__global__ __launch_bounds__(128, 3)
void lstm_fused_kernel(const float* __restrict__ x,
                       const float* __restrict__ Wi,
                       const float* __restrict__ Wh,
                       const float* __restrict__ bias,
                       const float* __restrict__ Wd,
                       const float* __restrict__ bd,
                       float* __restrict__ out)
{
    __shared__ float4 hsm4[4][4];  // per-warp h vector (16 floats), 16B aligned

    const int wib  = threadIdx.x >> 5;
    const int lane = threadIdx.x & 31;
    const int be   = blockIdx.x * 4 + wib;   // batch element
    const int colA = lane;        // i (lanes 0-15) / f (lanes 16-31)
    const int colB = lane + 32;   // g (lanes 0-15) / o (lanes 16-31)

    // Weights packed over adjacent k. [0..7] = Wi pairs, [8..15] = Wh pairs.
    u64 wA[16], wB[16];
#pragma unroll
    for (int m = 0; m < 8; ++m) {
        wA[m]     = pack2(Wi[(2*m) * NG + colA], Wi[(2*m+1) * NG + colA]);
        wB[m]     = pack2(Wi[(2*m) * NG + colB], Wi[(2*m+1) * NG + colB]);
        wA[8 + m] = pack2(Wh[(2*m) * NG + colA], Wh[(2*m+1) * NG + colA]);
        wB[8 + m] = pack2(Wh[(2*m) * NG + colB], Wh[(2*m+1) * NG + colB]);
    }
    const float bA = bias[colA];
    const float bB = bias[colB];

    const float L2E = 1.44269504088896340736f;
    // second-column activation: lanes<16 -> tanh(zB) = 2*sig(2 zB) - 1 ; lanes>=16 -> sig(zB)
    const float s2 = (lane < 16) ? (-2.f * L2E) : (-L2E);
    const float m2 = (lane < 16) ? 2.f : 1.f;
    const float a2 = (lane < 16) ? -1.f : 0.f;

    float* hrow = (float*)&hsm4[wib][0];
    if (lane < 16) hrow[lane] = 0.f;
    __syncwarp();

    const float4* xp = (const float4*)(x + (size_t)be * (NT * ND));
    float4 xc0 = xp[0], xc1 = xp[1], xc2 = xp[2], xc3 = xp[3];
    float c = 0.f;

    auto step = [&](const float4& v0, const float4& v1, const float4& v2v, const float4& v3) {
        // h pairs from shared (broadcast LDS.128)
        float4 h0 = hsm4[wib][0], h1 = hsm4[wib][1], h2 = hsm4[wib][2], h3 = hsm4[wib][3];
        u64 hp[8];
        hp[0] = pack2(h0.x, h0.y); hp[1] = pack2(h0.z, h0.w);
        hp[2] = pack2(h1.x, h1.y); hp[3] = pack2(h1.z, h1.w);
        hp[4] = pack2(h2.x, h2.y); hp[5] = pack2(h2.z, h2.w);
        hp[6] = pack2(h3.x, h3.y); hp[7] = pack2(h3.z, h3.w);
        u64 xq[8];
        xq[0] = pack2(v0.x, v0.y); xq[1] = pack2(v0.z, v0.w);
        xq[2] = pack2(v1.x, v1.y); xq[3] = pack2(v1.z, v1.w);
        xq[4] = pack2(v2v.x, v2v.y); xq[5] = pack2(v2v.z, v2v.w);
        xq[6] = pack2(v3.x, v3.y); xq[7] = pack2(v3.z, v3.w);

        u64 aA = pack2(bA, 0.f);
        u64 aB = pack2(bB, 0.f);
#pragma unroll
        for (int m = 0; m < 8; ++m) {
            aA = ffma2(hp[m], wA[8 + m], aA);
            aB = ffma2(hp[m], wB[8 + m], aB);
        }
#pragma unroll
        for (int m = 0; m < 8; ++m) {
            aA = ffma2(xq[m], wA[m], aA);
            aB = ffma2(xq[m], wB[m], aB);
        }
        float zA, zAh, zB, zBh;
        unpack2(aA, zA, zAh); zA += zAh;
        unpack2(aB, zB, zBh); zB += zBh;

        float v1g = rcpf(1.f + ex2f(-L2E * zA));                 // sig(i) / sig(f)
        float v2g = fmaf(m2, rcpf(1.f + ex2f(s2 * zB)), a2);     // tanh(g) / sig(o)

        float sf = __shfl_down_sync(0xffffffffu, v1g, 16);       // sig(f) -> lanes 0-15
        float so = __shfl_down_sync(0xffffffffu, v2g, 16);       // sig(o) -> lanes 0-15

        c = fmaf(sf, c, v1g * v2g);                              // valid lanes 0-15
        float th = fmaf(2.f, rcpf(1.f + ex2f(-2.f * L2E * c)), -1.f);  // tanh(c)
        float hnew = so * th;

        __syncwarp();                 // all lanes done reading old h
        if (lane < 16) hrow[lane] = hnew;
        __syncwarp();                 // new h visible
    };

#pragma unroll 1
    for (int t = 0; t < NT; t += 2) {
        // prefetch t+1 while computing t
        const float4* q1 = xp + (t + 1) * 4;
        float4 xn0 = q1[0], xn1 = q1[1], xn2 = q1[2], xn3 = q1[3];
        step(xc0, xc1, xc2, xc3);

        // prefetch t+2 (clamped) while computing t+1
        int tp = (t + 2 < NT) ? (t + 2) : (NT - 1);
        const float4* q2 = xp + tp * 4;
        xc0 = q2[0]; xc1 = q2[1]; xc2 = q2[2]; xc3 = q2[3];
        step(xn0, xn1, xn2, xn3);
    }

    // head: logits = c_T @ Wd + bd, then 2-way softmax (lanes 0-15 hold c)
    float p0 = 0.f, p1 = 0.f;
    if (lane < 16) {
        p0 = c * Wd[2 * lane];
        p1 = c * Wd[2 * lane + 1];
    }
#pragma unroll
    for (int off = 8; off; off >>= 1) {
        p0 += __shfl_xor_sync(0xffffffffu, p0, off);
        p1 += __shfl_xor_sync(0xffffffffu, p1, off);
    }
    if (lane == 0) {
        float l0 = p0 + bd[0];
        float l1 = p1 + bd[1];
        float mx = fmaxf(l0, l1);
        float e0 = ex2f((l0 - mx) * L2E);
        float e1 = ex2f((l1 - mx) * L2E);
        float inv = rcpf(e0 + e1);
        out[2 * be]     = e0 * inv;
        out[2 * be + 1] = e1 * inv;
    }
}

extern "C" void kernel_launch(void* const* d_in, const int* in_sizes, int n_in,
                              void* d_out, int out_size)
{
    const float* x  = (const float*)d_in[0];
    const float* Wi = (const float*)d_in[1];
    const float* Wh = (const float*)d_in[2];
    const float* b  = (const float*)d_in[3];
    const float* Wd = (const float*)d_in[4];
    const float* bd = (const float*)d_in[5];
    float* out = (float*)d_out;

    lstm_fused_kernel<<<NB / 4, 128>>>(x, Wi, Wh, b, Wd, bd, out);
}

// round 2
// speedup vs baseline: 1.1311x; 1.1311x over previous
#include <cuda_runtime.h>
#include <cstdint>

// CarryLSTMModel: B=8192, T=1024, D=16, H=16 (4H=64 gates, order i,f,g,o)
// One warp per batch element. Lane j owns gate columns j and j+32.
// - All weights register-resident as f32x2 pairs over adjacent k (fma.rn.f32x2).
// - h-exchange via 16 warp shuffles (no smem, no syncwarp).
// - Weights/bias pre-scaled by the sigmoid exponent constant per lane.
// - Split x-chain / h-chain accumulators (depth 8 each) merged with add.rn.f32x2.

#define NB 8192
#define NT 1024
#define ND 16
#define NG 64

typedef unsigned long long u64;
typedef unsigned int u32;

__device__ __forceinline__ u64 pack2(float lo, float hi) {
    u64 r;
    asm("mov.b64 %0, {%1, %2};" : "=l"(r) : "r"(__float_as_uint(lo)), "r"(__float_as_uint(hi)));
    return r;
}
__device__ __forceinline__ void unpack2(u64 v, float& lo, float& hi) {
    u32 a, b;
    asm("mov.b64 {%0, %1}, %2;" : "=r"(a), "=r"(b) : "l"(v));
    lo = __uint_as_float(a);
    hi = __uint_as_float(b);
}
__device__ __forceinline__ u64 ffma2(u64 a, u64 b, u64 c) {
    u64 d;
    asm("fma.rn.f32x2 %0, %1, %2, %3;" : "=l"(d) : "l"(a), "l"(b), "l"(c));
    return d;
}
__device__ __forceinline__ u64 fadd2(u64 a, u64 b) {
    u64 d;
    asm("add.rn.f32x2 %0, %1, %2;" : "=l"(d) : "l"(a), "l"(b));
    return d;
}
__device__ __forceinline__ float ex2f(float x) {
    float r; asm("ex2.approx.f32 %0, %1;" : "=f"(r) : "f"(x)); return r;
}
__device__ __forceinline__ float rcpf(float x) {
    float r; asm("rcp.approx.f32 %0, %1;" : "=f"(r) : "f"(x)); return r;
}

__global__ __launch_bounds__(128, 4)
void lstm_fused_kernel(const float* __restrict__ x,
                       const float* __restrict__ Wi,
                       const float* __restrict__ Wh,
                       const float* __restrict__ bias,
                       const float* __restrict__ Wd,
                       const float* __restrict__ bd,
                       float* __restrict__ out)
{
    const int wib  = threadIdx.x >> 5;
    const int lane = threadIdx.x & 31;
    const int be   = blockIdx.x * 4 + wib;   // batch element
    const int colA = lane;        // i (lanes 0-15) / f (lanes 16-31)
    const int colB = lane + 32;   // g (lanes 0-15) / o (lanes 16-31)

    const float L2E = 1.44269504088896340736f;
    // Pre-scale so the accumulated z is already the ex2 argument of the sigmoid:
    //   colA: sig(zA)  -> arg = -L2E * zA
    //   colB: lanes<16 tanh(zB)=2*sig(2 zB)-1 -> arg = -2*L2E*zB ; lanes>=16 sig(zB)
    const float sA = -L2E;
    const float sB = (lane < 16) ? (-2.f * L2E) : (-L2E);
    const float m2 = (lane < 16) ? 2.f : 1.f;
    const float a2 = (lane < 16) ? -1.f : 0.f;

    // Weights packed over adjacent k. [0..7] = Wi pairs, [8..15] = Wh pairs.
    u64 wA[16], wB[16];
#pragma unroll
    for (int m = 0; m < 8; ++m) {
        wA[m]     = pack2(Wi[(2*m) * NG + colA] * sA, Wi[(2*m+1) * NG + colA] * sA);
        wB[m]     = pack2(Wi[(2*m) * NG + colB] * sB, Wi[(2*m+1) * NG + colB] * sB);
        wA[8 + m] = pack2(Wh[(2*m) * NG + colA] * sA, Wh[(2*m+1) * NG + colA] * sA);
        wB[8 + m] = pack2(Wh[(2*m) * NG + colB] * sB, Wh[(2*m+1) * NG + colB] * sB);
    }
    const float bA = bias[colA] * sA;
    const float bB = bias[colB] * sB;

    const float4* xp = (const float4*)(x + (size_t)be * (NT * ND));
    float4 xc0 = xp[0], xc1 = xp[1], xc2 = xp[2], xc3 = xp[3];
    float c = 0.f;
    float hcur = 0.f;   // h value owned by lanes 0-15 (garbage elsewhere)

    auto step = [&](const float4& v0, const float4& v1, const float4& v2v, const float4& v3) {
        // --- x-part chains (independent of h, start immediately) ---
        u64 aAx = pack2(bA, 0.f);
        u64 aBx = pack2(bB, 0.f);
        {
            u64 q;
            q = pack2(v0.x, v0.y);  aAx = ffma2(q, wA[0], aAx); aBx = ffma2(q, wB[0], aBx);
            q = pack2(v0.z, v0.w);  aAx = ffma2(q, wA[1], aAx); aBx = ffma2(q, wB[1], aBx);
            q = pack2(v1.x, v1.y);  aAx = ffma2(q, wA[2], aAx); aBx = ffma2(q, wB[2], aBx);
            q = pack2(v1.z, v1.w);  aAx = ffma2(q, wA[3], aAx); aBx = ffma2(q, wB[3], aBx);
            q = pack2(v2v.x, v2v.y); aAx = ffma2(q, wA[4], aAx); aBx = ffma2(q, wB[4], aBx);
            q = pack2(v2v.z, v2v.w); aAx = ffma2(q, wA[5], aAx); aBx = ffma2(q, wB[5], aBx);
            q = pack2(v3.x, v3.y);  aAx = ffma2(q, wA[6], aAx); aBx = ffma2(q, wB[6], aBx);
            q = pack2(v3.z, v3.w);  aAx = ffma2(q, wA[7], aAx); aBx = ffma2(q, wB[7], aBx);
        }

        // --- h-part chains via warp broadcast (no smem, no syncs) ---
        u64 aAh = 0, aBh = 0;   // 0x0 == packed {0.f, 0.f}
#pragma unroll
        for (int m = 0; m < 8; ++m) {
            float ha = __shfl_sync(0xffffffffu, hcur, 2 * m);
            float hb = __shfl_sync(0xffffffffu, hcur, 2 * m + 1);
            u64 hv = pack2(ha, hb);
            aAh = ffma2(hv, wA[8 + m], aAh);
            aBh = ffma2(hv, wB[8 + m], aBh);
        }

        u64 sAacc = fadd2(aAx, aAh);
        u64 sBacc = fadd2(aBx, aBh);
        float zA, zAh, zB, zBh;
        unpack2(sAacc, zA, zAh); zA += zAh;   // = -L2E * (x.Wi + h.Wh + b)_colA
        unpack2(sBacc, zB, zBh); zB += zBh;   // = sB * (...)_colB

        float v1g = rcpf(1.f + ex2f(zA));                 // sig(i) / sig(f)
        float v2g = fmaf(m2, rcpf(1.f + ex2f(zB)), a2);   // tanh(g) / sig(o)

        float sf = __shfl_down_sync(0xffffffffu, v1g, 16);  // sig(f) -> lanes 0-15
        float so = __shfl_down_sync(0xffffffffu, v2g, 16);  // sig(o) -> lanes 0-15

        c = fmaf(sf, c, v1g * v2g);                                     // lanes 0-15 valid
        float th = fmaf(2.f, rcpf(1.f + ex2f(-2.f * L2E * c)), -1.f);   // tanh(c)
        hcur = so * th;                                                 // new h (lanes 0-15)
    };

#pragma unroll 1
    for (int t = 0; t < NT; t += 2) {
        // prefetch t+1 while computing t
        const float4* q1 = xp + (t + 1) * 4;
        float4 xn0 = q1[0], xn1 = q1[1], xn2 = q1[2], xn3 = q1[3];
        step(xc0, xc1, xc2, xc3);

        // prefetch t+2 (clamped) while computing t+1
        int tp = (t + 2 < NT) ? (t + 2) : (NT - 1);
        const float4* q2 = xp + tp * 4;
        xc0 = q2[0]; xc1 = q2[1]; xc2 = q2[2]; xc3 = q2[3];
        step(xn0, xn1, xn2, xn3);
    }

    // head: logits = c_T @ Wd + bd, then 2-way softmax (lanes 0-15 hold c)
    float p0 = 0.f, p1 = 0.f;
    if (lane < 16) {
        p0 = c * Wd[2 * lane];
        p1 = c * Wd[2 * lane + 1];
    }
#pragma unroll
    for (int off = 8; off; off >>= 1) {
        p0 += __shfl_xor_sync(0xffffffffu, p0, off);
        p1 += __shfl_xor_sync(0xffffffffu, p1, off);
    }
    if (lane == 0) {
        float l0 = p0 + bd[0];
        float l1 = p1 + bd[1];
        float mx = fmaxf(l0, l1);
        float e0 = ex2f((l0 - mx) * L2E);
        float e1 = ex2f((l1 - mx) * L2E);
        float inv = rcpf(e0 + e1);
        out[2 * be]     = e0 * inv;
        out[2 * be + 1] = e1 * inv;
    }
}

extern "C" void kernel_launch(void* const* d_in, const int* in_sizes, int n_in,
                              void* d_out, int out_size)
{
    const float* x  = (const float*)d_in[0];
    const float* Wi = (const float*)d_in[1];
    const float* Wh = (const float*)d_in[2];
    const float* b  = (const float*)d_in[3];
    const float* Wd = (const float*)d_in[4];
    const float* bd = (const float*)d_in[5];
    float* out = (float*)d_out;

    lstm_fused_kernel<<<NB / 4, 128>>>(x, Wi, Wh, b, Wd, bd, out);
}

// round 3
// speedup vs baseline: 1.1811x; 1.0442x over previous
#include <cuda_runtime.h>
#include <cstdint>

// CarryLSTMModel: B=8192, T=1024, D=16, H=16 (4H=64 gates, order i,f,g,o)
// 16 lanes per batch element, 2 elements per warp (lanes 0-15 / 16-31).
// Lane j owns gate columns {j, j+16, j+32, j+48} = (i_j, f_j, g_j, o_j),
// so c[j], h[j] are lane-local (no shfl_down for gate combine).
// h-broadcast: width-16 shuffles, one instruction serves both elements
// -> 8 SHFL per element-step (minimum possible).
// All weights register-resident as f32x2 pairs over adjacent k, pre-scaled
// by the activation exponent constant (-log2e for i/f/o, -2log2e for g).

#define NB 8192
#define NT 1024
#define ND 16
#define NG 64

typedef unsigned long long u64;
typedef unsigned int u32;

__device__ __forceinline__ u64 pack2(float lo, float hi) {
    u64 r;
    asm("mov.b64 %0, {%1, %2};" : "=l"(r) : "r"(__float_as_uint(lo)), "r"(__float_as_uint(hi)));
    return r;
}
__device__ __forceinline__ void unpack2(u64 v, float& lo, float& hi) {
    u32 a, b;
    asm("mov.b64 {%0, %1}, %2;" : "=r"(a), "=r"(b) : "l"(v));
    lo = __uint_as_float(a);
    hi = __uint_as_float(b);
}
__device__ __forceinline__ u64 ffma2(u64 a, u64 b, u64 c) {
    u64 d;
    asm("fma.rn.f32x2 %0, %1, %2, %3;" : "=l"(d) : "l"(a), "l"(b), "l"(c));
    return d;
}
__device__ __forceinline__ float ex2f(float x) {
    float r; asm("ex2.approx.f32 %0, %1;" : "=f"(r) : "f"(x)); return r;
}
__device__ __forceinline__ float rcpf(float x) {
    float r; asm("rcp.approx.f32 %0, %1;" : "=f"(r) : "f"(x)); return r;
}

__global__ __launch_bounds__(128, 2)
void lstm_fused_kernel(const float* __restrict__ x,
                       const float* __restrict__ Wi,
                       const float* __restrict__ Wh,
                       const float* __restrict__ bias,
                       const float* __restrict__ Wd,
                       const float* __restrict__ bd,
                       float* __restrict__ out)
{
    const int wib  = threadIdx.x >> 5;
    const int lane = threadIdx.x & 31;
    const int half = lane >> 4;          // 0 or 1: which element in the warp
    const int j    = lane & 15;          // gate index owned by this lane
    const int be   = blockIdx.x * 8 + wib * 2 + half;   // batch element

    const float L2E = 1.44269504088896340736f;
    // column set: ci=j (i), cf=j+16 (f), cg=j+32 (g), co=j+48 (o)
    // pre-scale: z already equals the ex2 argument of the activation
    const float sI = -L2E, sF = -L2E, sG = -2.f * L2E, sO = -L2E;
    const int ci = j, cf = j + 16, cg = j + 32, co = j + 48;

    // weights as f32x2 pairs over adjacent k: [0..7]=Wi pairs, [8..15]=Wh pairs
    u64 wI[16], wF[16], wG[16], wO[16];
#pragma unroll
    for (int m = 0; m < 8; ++m) {
        wI[m]     = pack2(Wi[(2*m) * NG + ci] * sI, Wi[(2*m+1) * NG + ci] * sI);
        wF[m]     = pack2(Wi[(2*m) * NG + cf] * sF, Wi[(2*m+1) * NG + cf] * sF);
        wG[m]     = pack2(Wi[(2*m) * NG + cg] * sG, Wi[(2*m+1) * NG + cg] * sG);
        wO[m]     = pack2(Wi[(2*m) * NG + co] * sO, Wi[(2*m+1) * NG + co] * sO);
        wI[8 + m] = pack2(Wh[(2*m) * NG + ci] * sI, Wh[(2*m+1) * NG + ci] * sI);
        wF[8 + m] = pack2(Wh[(2*m) * NG + cf] * sF, Wh[(2*m+1) * NG + cf] * sF);
        wG[8 + m] = pack2(Wh[(2*m) * NG + cg] * sG, Wh[(2*m+1) * NG + cg] * sG);
        wO[8 + m] = pack2(Wh[(2*m) * NG + co] * sO, Wh[(2*m+1) * NG + co] * sO);
    }
    const float bI = bias[ci] * sI;
    const float bF = bias[cf] * sF;
    const float bG = bias[cg] * sG;
    const float bO = bias[co] * sO;

    const float4* xp = (const float4*)(x + (size_t)be * (NT * ND));
    float4 xc0 = xp[0], xc1 = xp[1], xc2 = xp[2], xc3 = xp[3];
    float c = 0.f;      // cell state for gate index j of this element
    float hcur = 0.f;   // hidden state h[j] of this element

    auto step = [&](const float4& v0, const float4& v1, const float4& v2v, const float4& v3) {
        // --- h broadcast: width-16 shuffle serves both elements at once ---
        u64 hp[8];
#pragma unroll
        for (int m = 0; m < 8; ++m) {
            float ha = __shfl_sync(0xffffffffu, hcur, 2 * m,     16);
            float hb = __shfl_sync(0xffffffffu, hcur, 2 * m + 1, 16);
            hp[m] = pack2(ha, hb);
        }

        u64 xq[8];
        xq[0] = pack2(v0.x, v0.y);  xq[1] = pack2(v0.z, v0.w);
        xq[2] = pack2(v1.x, v1.y);  xq[3] = pack2(v1.z, v1.w);
        xq[4] = pack2(v2v.x, v2v.y); xq[5] = pack2(v2v.z, v2v.w);
        xq[6] = pack2(v3.x, v3.y);  xq[7] = pack2(v3.z, v3.w);

        u64 aI = pack2(bI, 0.f);
        u64 aF = pack2(bF, 0.f);
        u64 aG = pack2(bG, 0.f);
        u64 aO = pack2(bO, 0.f);
#pragma unroll
        for (int m = 0; m < 8; ++m) {
            aI = ffma2(xq[m], wI[m], aI);
            aF = ffma2(xq[m], wF[m], aF);
            aG = ffma2(xq[m], wG[m], aG);
            aO = ffma2(xq[m], wO[m], aO);
        }
#pragma unroll
        for (int m = 0; m < 8; ++m) {
            aI = ffma2(hp[m], wI[8 + m], aI);
            aF = ffma2(hp[m], wF[8 + m], aF);
            aG = ffma2(hp[m], wG[8 + m], aG);
            aO = ffma2(hp[m], wO[8 + m], aO);
        }
        float lo, hi, zI, zF, zG, zO;
        unpack2(aI, lo, hi); zI = lo + hi;
        unpack2(aF, lo, hi); zF = lo + hi;
        unpack2(aG, lo, hi); zG = lo + hi;
        unpack2(aO, lo, hi); zO = lo + hi;

        float vI = rcpf(1.f + ex2f(zI));                  // sig(i)
        float vF = rcpf(1.f + ex2f(zF));                  // sig(f)
        float vG = fmaf(2.f, rcpf(1.f + ex2f(zG)), -1.f); // tanh(g)
        float vO = rcpf(1.f + ex2f(zO));                  // sig(o)

        c = fmaf(vF, c, vI * vG);
        float tc = fmaf(2.f, rcpf(1.f + ex2f(-2.f * L2E * c)), -1.f);  // tanh(c)
        hcur = vO * tc;
    };

#pragma unroll 1
    for (int t = 0; t < NT; t += 2) {
        const float4* q1 = xp + (t + 1) * 4;
        float4 xn0 = q1[0], xn1 = q1[1], xn2 = q1[2], xn3 = q1[3];
        step(xc0, xc1, xc2, xc3);

        int tp = (t + 2 < NT) ? (t + 2) : (NT - 1);
        const float4* q2 = xp + tp * 4;
        xc0 = q2[0]; xc1 = q2[1]; xc2 = q2[2]; xc3 = q2[3];
        step(xn0, xn1, xn2, xn3);
    }

    // head: logits = c_T @ Wd + bd, softmax over 2 classes.
    // Each half reduces its own 16 lanes (width-16 xor shuffles).
    float p0 = c * Wd[2 * j];
    float p1 = c * Wd[2 * j + 1];
#pragma unroll
    for (int off = 8; off; off >>= 1) {
        p0 += __shfl_xor_sync(0xffffffffu, p0, off, 16);
        p1 += __shfl_xor_sync(0xffffffffu, p1, off, 16);
    }
    if (j == 0) {
        float l0 = p0 + bd[0];
        float l1 = p1 + bd[1];
        float mx = fmaxf(l0, l1);
        float e0 = ex2f((l0 - mx) * L2E);
        float e1 = ex2f((l1 - mx) * L2E);
        float inv = rcpf(e0 + e1);
        out[2 * be]     = e0 * inv;
        out[2 * be + 1] = e1 * inv;
    }
}

extern "C" void kernel_launch(void* const* d_in, const int* in_sizes, int n_in,
                              void* d_out, int out_size)
{
    const float* x  = (const float*)d_in[0];
    const float* Wi = (const float*)d_in[1];
    const float* Wh = (const float*)d_in[2];
    const float* b  = (const float*)d_in[3];
    const float* Wd = (const float*)d_in[4];
    const float* bd = (const float*)d_in[5];
    float* out = (float*)d_out;

    lstm_fused_kernel<<<NB / 8, 128>>>(x, Wi, Wh, b, Wd, bd, out);
}

// round 4
// speedup vs baseline: 1.3213x; 1.1187x over previous
#include <cuda_runtime.h>
#include <cstdint>

// CarryLSTMModel: B=8192, T=1024, D=16, H=16 (4H=64 gates, order i,f,g,o)
// 16 lanes per batch element, 2 elements per HALF-warp slot, 2 per lane:
// -> 4 batch elements per warp. Lane j (=lane&15) owns gate columns
// {j, j+16, j+32, j+48} for BOTH of its elements; weights shared (no dup cost).
// h-broadcast: width-16 shuffles serve both warp halves -> 4 SHFL/elem-step.
// All weights register-resident as f32x2 pairs over adjacent k, pre-scaled by
// the activation exponent constant (-log2e for i/f/o, -2log2e for g).

#define NB 8192
#define NT 1024
#define ND 16
#define NG 64

typedef unsigned long long u64;
typedef unsigned int u32;

__device__ __forceinline__ u64 pack2(float lo, float hi) {
    u64 r;
    asm("mov.b64 %0, {%1, %2};" : "=l"(r) : "r"(__float_as_uint(lo)), "r"(__float_as_uint(hi)));
    return r;
}
__device__ __forceinline__ void unpack2(u64 v, float& lo, float& hi) {
    u32 a, b;
    asm("mov.b64 {%0, %1}, %2;" : "=r"(a), "=r"(b) : "l"(v));
    lo = __uint_as_float(a);
    hi = __uint_as_float(b);
}
__device__ __forceinline__ u64 ffma2(u64 a, u64 b, u64 c) {
    u64 d;
    asm("fma.rn.f32x2 %0, %1, %2, %3;" : "=l"(d) : "l"(a), "l"(b), "l"(c));
    return d;
}
__device__ __forceinline__ float ex2f(float x) {
    float r; asm("ex2.approx.f32 %0, %1;" : "=f"(r) : "f"(x)); return r;
}
__device__ __forceinline__ float rcpf(float x) {
    float r; asm("rcp.approx.f32 %0, %1;" : "=f"(r) : "f"(x)); return r;
}

__global__ __launch_bounds__(128, 2)
void lstm_fused_kernel(const float* __restrict__ x,
                       const float* __restrict__ Wi,
                       const float* __restrict__ Wh,
                       const float* __restrict__ bias,
                       const float* __restrict__ Wd,
                       const float* __restrict__ bd,
                       float* __restrict__ out)
{
    const int wib  = threadIdx.x >> 5;
    const int lane = threadIdx.x & 31;
    const int half = lane >> 4;          // 0 or 1: which half of the warp
    const int j    = lane & 15;          // gate index owned by this lane
    const int base = blockIdx.x * 16 + wib * 4 + half * 2;  // this lane's 2 elements

    const float L2E = 1.44269504088896340736f;
    const float sI = -L2E, sF = -L2E, sG = -2.f * L2E, sO = -L2E;
    const int ci = j, cf = j + 16, cg = j + 32, co = j + 48;

    // weights as f32x2 pairs over adjacent k: [0..7]=Wi pairs, [8..15]=Wh pairs
    u64 wI[16], wF[16], wG[16], wO[16];
#pragma unroll
    for (int m = 0; m < 8; ++m) {
        wI[m]     = pack2(Wi[(2*m) * NG + ci] * sI, Wi[(2*m+1) * NG + ci] * sI);
        wF[m]     = pack2(Wi[(2*m) * NG + cf] * sF, Wi[(2*m+1) * NG + cf] * sF);
        wG[m]     = pack2(Wi[(2*m) * NG + cg] * sG, Wi[(2*m+1) * NG + cg] * sG);
        wO[m]     = pack2(Wi[(2*m) * NG + co] * sO, Wi[(2*m+1) * NG + co] * sO);
        wI[8 + m] = pack2(Wh[(2*m) * NG + ci] * sI, Wh[(2*m+1) * NG + ci] * sI);
        wF[8 + m] = pack2(Wh[(2*m) * NG + cf] * sF, Wh[(2*m+1) * NG + cf] * sF);
        wG[8 + m] = pack2(Wh[(2*m) * NG + cg] * sG, Wh[(2*m+1) * NG + cg] * sG);
        wO[8 + m] = pack2(Wh[(2*m) * NG + co] * sO, Wh[(2*m+1) * NG + co] * sO);
    }
    const float bI = bias[ci] * sI;
    const float bF = bias[cf] * sF;
    const float bG = bias[cg] * sG;
    const float bO = bias[co] * sO;

    const float4* xp0 = (const float4*)(x + (size_t)(base + 0) * (NT * ND));
    const float4* xp1 = (const float4*)(x + (size_t)(base + 1) * (NT * ND));

    float c0 = 0.f, c1 = 0.f;     // cell states (gate index j) of the 2 elements
    float h0 = 0.f, h1 = 0.f;     // hidden states h[j] of the 2 elements

    float4 a0 = xp0[0], a1 = xp0[1], a2 = xp0[2], a3 = xp0[3];   // elem0 cur x
    float4 e0 = xp1[0], e1 = xp1[1], e2 = xp1[2], e3 = xp1[3];   // elem1 cur x

    auto step = [&](const float4& u0, const float4& u1, const float4& u2, const float4& u3,
                    const float4& v0, const float4& v1, const float4& v2, const float4& v3) {
        // --- h broadcasts: width-16 shuffle serves both warp halves ---
        u64 hp0[8], hp1[8];
#pragma unroll
        for (int m = 0; m < 8; ++m) {
            float a = __shfl_sync(0xffffffffu, h0, 2 * m,     16);
            float b = __shfl_sync(0xffffffffu, h0, 2 * m + 1, 16);
            hp0[m] = pack2(a, b);
            float p = __shfl_sync(0xffffffffu, h1, 2 * m,     16);
            float q = __shfl_sync(0xffffffffu, h1, 2 * m + 1, 16);
            hp1[m] = pack2(p, q);
        }

        u64 xq0[8], xq1[8];
        xq0[0] = pack2(u0.x, u0.y); xq0[1] = pack2(u0.z, u0.w);
        xq0[2] = pack2(u1.x, u1.y); xq0[3] = pack2(u1.z, u1.w);
        xq0[4] = pack2(u2.x, u2.y); xq0[5] = pack2(u2.z, u2.w);
        xq0[6] = pack2(u3.x, u3.y); xq0[7] = pack2(u3.z, u3.w);
        xq1[0] = pack2(v0.x, v0.y); xq1[1] = pack2(v0.z, v0.w);
        xq1[2] = pack2(v1.x, v1.y); xq1[3] = pack2(v1.z, v1.w);
        xq1[4] = pack2(v2.x, v2.y); xq1[5] = pack2(v2.z, v2.w);
        xq1[6] = pack2(v3.x, v3.y); xq1[7] = pack2(v3.z, v3.w);

        u64 aI0 = pack2(bI, 0.f), aF0 = pack2(bF, 0.f), aG0 = pack2(bG, 0.f), aO0 = pack2(bO, 0.f);
        u64 aI1 = aI0, aF1 = aF0, aG1 = aG0, aO1 = aO0;
#pragma unroll
        for (int m = 0; m < 8; ++m) {
            aI0 = ffma2(xq0[m], wI[m], aI0);
            aF0 = ffma2(xq0[m], wF[m], aF0);
            aG0 = ffma2(xq0[m], wG[m], aG0);
            aO0 = ffma2(xq0[m], wO[m], aO0);
            aI1 = ffma2(xq1[m], wI[m], aI1);
            aF1 = ffma2(xq1[m], wF[m], aF1);
            aG1 = ffma2(xq1[m], wG[m], aG1);
            aO1 = ffma2(xq1[m], wO[m], aO1);
        }
#pragma unroll
        for (int m = 0; m < 8; ++m) {
            aI0 = ffma2(hp0[m], wI[8 + m], aI0);
            aF0 = ffma2(hp0[m], wF[8 + m], aF0);
            aG0 = ffma2(hp0[m], wG[8 + m], aG0);
            aO0 = ffma2(hp0[m], wO[8 + m], aO0);
            aI1 = ffma2(hp1[m], wI[8 + m], aI1);
            aF1 = ffma2(hp1[m], wF[8 + m], aF1);
            aG1 = ffma2(hp1[m], wG[8 + m], aG1);
            aO1 = ffma2(hp1[m], wO[8 + m], aO1);
        }

        float lo, hi, zI, zF, zG, zO;
        // element 0
        unpack2(aI0, lo, hi); zI = lo + hi;
        unpack2(aF0, lo, hi); zF = lo + hi;
        unpack2(aG0, lo, hi); zG = lo + hi;
        unpack2(aO0, lo, hi); zO = lo + hi;
        {
            float vI = rcpf(1.f + ex2f(zI));
            float vF = rcpf(1.f + ex2f(zF));
            float vG = fmaf(2.f, rcpf(1.f + ex2f(zG)), -1.f);
            float vO = rcpf(1.f + ex2f(zO));
            c0 = fmaf(vF, c0, vI * vG);
            float tc = fmaf(2.f, rcpf(1.f + ex2f(-2.f * L2E * c0)), -1.f);
            h0 = vO * tc;
        }
        // element 1
        unpack2(aI1, lo, hi); zI = lo + hi;
        unpack2(aF1, lo, hi); zF = lo + hi;
        unpack2(aG1, lo, hi); zG = lo + hi;
        unpack2(aO1, lo, hi); zO = lo + hi;
        {
            float vI = rcpf(1.f + ex2f(zI));
            float vF = rcpf(1.f + ex2f(zF));
            float vG = fmaf(2.f, rcpf(1.f + ex2f(zG)), -1.f);
            float vO = rcpf(1.f + ex2f(zO));
            c1 = fmaf(vF, c1, vI * vG);
            float tc = fmaf(2.f, rcpf(1.f + ex2f(-2.f * L2E * c1)), -1.f);
            h1 = vO * tc;
        }
    };

#pragma unroll 1
    for (int t = 0; t < NT; t += 2) {
        // prefetch t+1 for both elements while computing t
        const float4* q0 = xp0 + (t + 1) * 4;
        const float4* q1 = xp1 + (t + 1) * 4;
        float4 n0 = q0[0], n1 = q0[1], n2 = q0[2], n3 = q0[3];
        float4 m0 = q1[0], m1 = q1[1], m2 = q1[2], m3 = q1[3];
        step(a0, a1, a2, a3, e0, e1, e2, e3);

        // prefetch t+2 (clamped) while computing t+1
        int tp = (t + 2 < NT) ? (t + 2) : (NT - 1);
        const float4* r0 = xp0 + tp * 4;
        const float4* r1 = xp1 + tp * 4;
        a0 = r0[0]; a1 = r0[1]; a2 = r0[2]; a3 = r0[3];
        e0 = r1[0]; e1 = r1[1]; e2 = r1[2]; e3 = r1[3];
        step(n0, n1, n2, n3, m0, m1, m2, m3);
    }

    // head: logits = c_T @ Wd + bd, softmax over 2 classes. width-16 reductions.
    const float wd0 = Wd[2 * j], wd1 = Wd[2 * j + 1];
    float p00 = c0 * wd0, p01 = c0 * wd1;
    float p10 = c1 * wd0, p11 = c1 * wd1;
#pragma unroll
    for (int off = 8; off; off >>= 1) {
        p00 += __shfl_xor_sync(0xffffffffu, p00, off, 16);
        p01 += __shfl_xor_sync(0xffffffffu, p01, off, 16);
        p10 += __shfl_xor_sync(0xffffffffu, p10, off, 16);
        p11 += __shfl_xor_sync(0xffffffffu, p11, off, 16);
    }
    if (j == 0) {
        const float b0 = bd[0], b1 = bd[1];
        {
            float l0 = p00 + b0, l1 = p01 + b1;
            float mx = fmaxf(l0, l1);
            float q0v = ex2f((l0 - mx) * L2E);
            float q1v = ex2f((l1 - mx) * L2E);
            float inv = rcpf(q0v + q1v);
            out[2 * base]     = q0v * inv;
            out[2 * base + 1] = q1v * inv;
        }
        {
            float l0 = p10 + b0, l1 = p11 + b1;
            float mx = fmaxf(l0, l1);
            float q0v = ex2f((l0 - mx) * L2E);
            float q1v = ex2f((l1 - mx) * L2E);
            float inv = rcpf(q0v + q1v);
            out[2 * (base + 1)]     = q0v * inv;
            out[2 * (base + 1) + 1] = q1v * inv;
        }
    }
}

extern "C" void kernel_launch(void* const* d_in, const int* in_sizes, int n_in,
                              void* d_out, int out_size)
{
    const float* x  = (const float*)d_in[0];
    const float* Wi = (const float*)d_in[1];
    const float* Wh = (const float*)d_in[2];
    const float* b  = (const float*)d_in[3];
    const float* Wd = (const float*)d_in[4];
    const float* bd = (const float*)d_in[5];
    float* out = (float*)d_out;

    lstm_fused_kernel<<<NB / 16, 128>>>(x, Wi, Wh, b, Wd, bd, out);
}

// round 5
// speedup vs baseline: 1.6521x; 1.2503x over previous
#include <cuda_runtime.h>
#include <cstdint>

// CarryLSTMModel: B=8192, T=1024, D=16, H=16 (4H=64 gates, order i,f,g,o)
// 16 lanes per batch element, 4 batch elements per warp (2 per lane).
// Lane j (=lane&15) owns gate columns {j, j+16, j+32, j+48} for both elements.
// Weights register-resident as f32x2 pairs over adjacent k (fma.rn.f32x2).
// Activations via MUFU.TANH (tanh.approx.f32):
//   sig(z) = 0.5 + 0.5*tanh(z/2)  (i/f/o weights pre-scaled by 0.5)
//   tanh(g), tanh(c) direct.      -> 5 MUFU per element-step (was 10).

#define NB 8192
#define NT 1024
#define ND 16
#define NG 64

typedef unsigned long long u64;
typedef unsigned int u32;

__device__ __forceinline__ u64 pack2(float lo, float hi) {
    u64 r;
    asm("mov.b64 %0, {%1, %2};" : "=l"(r) : "r"(__float_as_uint(lo)), "r"(__float_as_uint(hi)));
    return r;
}
__device__ __forceinline__ void unpack2(u64 v, float& lo, float& hi) {
    u32 a, b;
    asm("mov.b64 {%0, %1}, %2;" : "=r"(a), "=r"(b) : "l"(v));
    lo = __uint_as_float(a);
    hi = __uint_as_float(b);
}
__device__ __forceinline__ u64 ffma2(u64 a, u64 b, u64 c) {
    u64 d;
    asm("fma.rn.f32x2 %0, %1, %2, %3;" : "=l"(d) : "l"(a), "l"(b), "l"(c));
    return d;
}
__device__ __forceinline__ float tanhap(float x) {
    float r; asm("tanh.approx.f32 %0, %1;" : "=f"(r) : "f"(x)); return r;
}
__device__ __forceinline__ float ex2f(float x) {
    float r; asm("ex2.approx.f32 %0, %1;" : "=f"(r) : "f"(x)); return r;
}
__device__ __forceinline__ float rcpf(float x) {
    float r; asm("rcp.approx.f32 %0, %1;" : "=f"(r) : "f"(x)); return r;
}

__global__ __launch_bounds__(128, 2)
void lstm_fused_kernel(const float* __restrict__ x,
                       const float* __restrict__ Wi,
                       const float* __restrict__ Wh,
                       const float* __restrict__ bias,
                       const float* __restrict__ Wd,
                       const float* __restrict__ bd,
                       float* __restrict__ out)
{
    const int wib  = threadIdx.x >> 5;
    const int lane = threadIdx.x & 31;
    const int half = lane >> 4;          // which half of the warp
    const int j    = lane & 15;          // gate index owned by this lane
    const int base = blockIdx.x * 16 + wib * 4 + half * 2;  // this lane's 2 elements

    // sig(z) = 0.5 + 0.5*tanh(z/2): accumulate z/2 directly for i/f/o.
    const float sI = 0.5f, sF = 0.5f, sG = 1.0f, sO = 0.5f;
    const int ci = j, cf = j + 16, cg = j + 32, co = j + 48;

    // weights as f32x2 pairs over adjacent k: [0..7]=Wi pairs, [8..15]=Wh pairs
    u64 wI[16], wF[16], wG[16], wO[16];
#pragma unroll
    for (int m = 0; m < 8; ++m) {
        wI[m]     = pack2(Wi[(2*m) * NG + ci] * sI, Wi[(2*m+1) * NG + ci] * sI);
        wF[m]     = pack2(Wi[(2*m) * NG + cf] * sF, Wi[(2*m+1) * NG + cf] * sF);
        wG[m]     = pack2(Wi[(2*m) * NG + cg] * sG, Wi[(2*m+1) * NG + cg] * sG);
        wO[m]     = pack2(Wi[(2*m) * NG + co] * sO, Wi[(2*m+1) * NG + co] * sO);
        wI[8 + m] = pack2(Wh[(2*m) * NG + ci] * sI, Wh[(2*m+1) * NG + ci] * sI);
        wF[8 + m] = pack2(Wh[(2*m) * NG + cf] * sF, Wh[(2*m+1) * NG + cf] * sF);
        wG[8 + m] = pack2(Wh[(2*m) * NG + cg] * sG, Wh[(2*m+1) * NG + cg] * sG);
        wO[8 + m] = pack2(Wh[(2*m) * NG + co] * sO, Wh[(2*m+1) * NG + co] * sO);
    }
    // bias as packed init constants (hoisted out of loop)
    const u64 bI2 = pack2(bias[ci] * sI, 0.f);
    const u64 bF2 = pack2(bias[cf] * sF, 0.f);
    const u64 bG2 = pack2(bias[cg] * sG, 0.f);
    const u64 bO2 = pack2(bias[co] * sO, 0.f);

    const float4* xp0 = (const float4*)(x + (size_t)(base + 0) * (NT * ND));
    const float4* xp1 = (const float4*)(x + (size_t)(base + 1) * (NT * ND));

    float c0 = 0.f, c1 = 0.f;
    float h0 = 0.f, h1 = 0.f;

    float4 a0 = xp0[0], a1 = xp0[1], a2 = xp0[2], a3 = xp0[3];   // elem0 cur x
    float4 e0 = xp1[0], e1 = xp1[1], e2 = xp1[2], e3 = xp1[3];   // elem1 cur x

    auto step = [&](const float4& u0, const float4& u1, const float4& u2, const float4& u3,
                    const float4& v0, const float4& v1, const float4& v2, const float4& v3) {
        // h broadcasts: width-16 shuffle serves both warp halves
        u64 hp0[8], hp1[8];
#pragma unroll
        for (int m = 0; m < 8; ++m) {
            float a = __shfl_sync(0xffffffffu, h0, 2 * m,     16);
            float b = __shfl_sync(0xffffffffu, h0, 2 * m + 1, 16);
            hp0[m] = pack2(a, b);
            float p = __shfl_sync(0xffffffffu, h1, 2 * m,     16);
            float q = __shfl_sync(0xffffffffu, h1, 2 * m + 1, 16);
            hp1[m] = pack2(p, q);
        }

        u64 xq0[8], xq1[8];
        xq0[0] = pack2(u0.x, u0.y); xq0[1] = pack2(u0.z, u0.w);
        xq0[2] = pack2(u1.x, u1.y); xq0[3] = pack2(u1.z, u1.w);
        xq0[4] = pack2(u2.x, u2.y); xq0[5] = pack2(u2.z, u2.w);
        xq0[6] = pack2(u3.x, u3.y); xq0[7] = pack2(u3.z, u3.w);
        xq1[0] = pack2(v0.x, v0.y); xq1[1] = pack2(v0.z, v0.w);
        xq1[2] = pack2(v1.x, v1.y); xq1[3] = pack2(v1.z, v1.w);
        xq1[4] = pack2(v2.x, v2.y); xq1[5] = pack2(v2.z, v2.w);
        xq1[6] = pack2(v3.x, v3.y); xq1[7] = pack2(v3.z, v3.w);

        u64 aI0 = bI2, aF0 = bF2, aG0 = bG2, aO0 = bO2;
        u64 aI1 = bI2, aF1 = bF2, aG1 = bG2, aO1 = bO2;
#pragma unroll
        for (int m = 0; m < 8; ++m) {
            aI0 = ffma2(xq0[m], wI[m], aI0);
            aF0 = ffma2(xq0[m], wF[m], aF0);
            aG0 = ffma2(xq0[m], wG[m], aG0);
            aO0 = ffma2(xq0[m], wO[m], aO0);
            aI1 = ffma2(xq1[m], wI[m], aI1);
            aF1 = ffma2(xq1[m], wF[m], aF1);
            aG1 = ffma2(xq1[m], wG[m], aG1);
            aO1 = ffma2(xq1[m], wO[m], aO1);
        }
#pragma unroll
        for (int m = 0; m < 8; ++m) {
            aI0 = ffma2(hp0[m], wI[8 + m], aI0);
            aF0 = ffma2(hp0[m], wF[8 + m], aF0);
            aG0 = ffma2(hp0[m], wG[8 + m], aG0);
            aO0 = ffma2(hp0[m], wO[8 + m], aO0);
            aI1 = ffma2(hp1[m], wI[8 + m], aI1);
            aF1 = ffma2(hp1[m], wF[8 + m], aF1);
            aG1 = ffma2(hp1[m], wG[8 + m], aG1);
            aO1 = ffma2(hp1[m], wO[8 + m], aO1);
        }

        float lo, hi, zI, zF, zG, zO;
        // element 0
        unpack2(aI0, lo, hi); zI = lo + hi;   // = z_i / 2
        unpack2(aF0, lo, hi); zF = lo + hi;   // = z_f / 2
        unpack2(aG0, lo, hi); zG = lo + hi;   // = z_g
        unpack2(aO0, lo, hi); zO = lo + hi;   // = z_o / 2
        {
            float vI = fmaf(0.5f, tanhap(zI), 0.5f);   // sig(z_i)
            float vF = fmaf(0.5f, tanhap(zF), 0.5f);   // sig(z_f)
            float vG = tanhap(zG);                     // tanh(z_g)
            float vO = fmaf(0.5f, tanhap(zO), 0.5f);   // sig(z_o)
            c0 = fmaf(vF, c0, vI * vG);
            h0 = vO * tanhap(c0);
        }
        // element 1
        unpack2(aI1, lo, hi); zI = lo + hi;
        unpack2(aF1, lo, hi); zF = lo + hi;
        unpack2(aG1, lo, hi); zG = lo + hi;
        unpack2(aO1, lo, hi); zO = lo + hi;
        {
            float vI = fmaf(0.5f, tanhap(zI), 0.5f);
            float vF = fmaf(0.5f, tanhap(zF), 0.5f);
            float vG = tanhap(zG);
            float vO = fmaf(0.5f, tanhap(zO), 0.5f);
            c1 = fmaf(vF, c1, vI * vG);
            h1 = vO * tanhap(c1);
        }
    };

#pragma unroll 1
    for (int t = 0; t < NT; t += 2) {
        // prefetch t+1 for both elements while computing t
        const float4* q0 = xp0 + (t + 1) * 4;
        const float4* q1 = xp1 + (t + 1) * 4;
        float4 n0 = q0[0], n1 = q0[1], n2 = q0[2], n3 = q0[3];
        float4 m0 = q1[0], m1 = q1[1], m2 = q1[2], m3 = q1[3];
        step(a0, a1, a2, a3, e0, e1, e2, e3);

        // prefetch t+2 (clamped) while computing t+1
        int tp = (t + 2 < NT) ? (t + 2) : (NT - 1);
        const float4* r0 = xp0 + tp * 4;
        const float4* r1 = xp1 + tp * 4;
        a0 = r0[0]; a1 = r0[1]; a2 = r0[2]; a3 = r0[3];
        e0 = r1[0]; e1 = r1[1]; e2 = r1[2]; e3 = r1[3];
        step(n0, n1, n2, n3, m0, m1, m2, m3);
    }

    // head: logits = c_T @ Wd + bd, softmax over 2 classes (exact math).
    const float L2E = 1.44269504088896340736f;
    const float wd0 = Wd[2 * j], wd1 = Wd[2 * j + 1];
    float p00 = c0 * wd0, p01 = c0 * wd1;
    float p10 = c1 * wd0, p11 = c1 * wd1;
#pragma unroll
    for (int off = 8; off; off >>= 1) {
        p00 += __shfl_xor_sync(0xffffffffu, p00, off, 16);
        p01 += __shfl_xor_sync(0xffffffffu, p01, off, 16);
        p10 += __shfl_xor_sync(0xffffffffu, p10, off, 16);
        p11 += __shfl_xor_sync(0xffffffffu, p11, off, 16);
    }
    if (j == 0) {
        const float b0 = bd[0], b1 = bd[1];
        {
            float l0 = p00 + b0, l1 = p01 + b1;
            float mx = fmaxf(l0, l1);
            float q0v = ex2f((l0 - mx) * L2E);
            float q1v = ex2f((l1 - mx) * L2E);
            float inv = rcpf(q0v + q1v);
            out[2 * base]     = q0v * inv;
            out[2 * base + 1] = q1v * inv;
        }
        {
            float l0 = p10 + b0, l1 = p11 + b1;
            float mx = fmaxf(l0, l1);
            float q0v = ex2f((l0 - mx) * L2E);
            float q1v = ex2f((l1 - mx) * L2E);
            float inv = rcpf(q0v + q1v);
            out[2 * (base + 1)]     = q0v * inv;
            out[2 * (base + 1) + 1] = q1v * inv;
        }
    }
}

extern "C" void kernel_launch(void* const* d_in, const int* in_sizes, int n_in,
                              void* d_out, int out_size)
{
    const float* x  = (const float*)d_in[0];
    const float* Wi = (const float*)d_in[1];
    const float* Wh = (const float*)d_in[2];
    const float* b  = (const float*)d_in[3];
    const float* Wd = (const float*)d_in[4];
    const float* bd = (const float*)d_in[5];
    float* out = (float*)d_out;

    lstm_fused_kernel<<<NB / 16, 128>>>(x, Wi, Wh, b, Wd, bd, out);
}